// round 7
// baseline (speedup 1.0000x reference)
#include <cuda_runtime.h>
#include <math_constants.h>

#define BN 4
#define TT 512
#define SS 512
#define IND 512
#define MD 256

// Scratch (allocation-free rule: __device__ globals)
__device__ float g_wq[BN * TT * MD];            // [b*T+t][d]
__device__ float g_uht[BN * MD * SS];           // [b][d][s]  (transposed uh)
__device__ float g_ctxp[2][BN * TT * MD];       // ctx split-K partials
__device__ float g_outp[3][BN * TT * IND];      // out split-K partials
__device__ float g_align_scratch[BN * TT * SS];

__device__ __forceinline__ float tanhap(float x) {
    float y;
    asm("tanh.approx.f32 %0, %1;" : "=f"(y) : "f"(x));
    return y;
}

// ---------------------------------------------------------------------------
// proj_kernel: z=0 -> g_wq = inputs @ Wq^T   (K=512)
//              z=1 -> g_uht[b][n][s] = mems @ Wc^T + bc, transposed (K=256)
// 128x64 block tile, 256 threads, 8x4 per thread, TK=8, register prefetch.
// ---------------------------------------------------------------------------
__global__ __launch_bounds__(256) void proj_kernel(
    const float* __restrict__ inputs, const float* __restrict__ mems,
    const float* __restrict__ Wq, const float* __restrict__ Wc,
    const float* __restrict__ bc)
{
    const int z = blockIdx.z;
    const float* A  = z ? mems : inputs;
    const float* Bm = z ? Wc : Wq;
    const int K = z ? MD : IND;

    __shared__ float As[8][132];
    __shared__ float Bs[8][68];

    const int tid = threadIdx.x;
    const int bm = blockIdx.y * 128;
    const int bn = blockIdx.x * 64;
    const int lrA = tid >> 1;
    const int lcA = (tid & 1) * 4;
    const int tx = tid & 15, ty = tid >> 4;
    const int n0 = tx * 4, m0 = ty * 8;

    float acc[8][4];
#pragma unroll
    for (int i = 0; i < 8; i++)
#pragma unroll
        for (int j = 0; j < 4; j++) acc[i][j] = 0.f;

    float4 a4 = *(const float4*)(A + (bm + lrA) * K + lcA);
    float4 b4 = make_float4(0.f, 0.f, 0.f, 0.f);
    if (tid < 128) b4 = *(const float4*)(Bm + (bn + lrA) * K + lcA);

    for (int k0 = 0; k0 < K; k0 += 8) {
        As[lcA + 0][lrA] = a4.x; As[lcA + 1][lrA] = a4.y;
        As[lcA + 2][lrA] = a4.z; As[lcA + 3][lrA] = a4.w;
        if (tid < 128) {
            Bs[lcA + 0][lrA] = b4.x; Bs[lcA + 1][lrA] = b4.y;
            Bs[lcA + 2][lrA] = b4.z; Bs[lcA + 3][lrA] = b4.w;
        }
        __syncthreads();
        const int kn = k0 + 8;
        if (kn < K) {
            a4 = *(const float4*)(A + (bm + lrA) * K + kn + lcA);
            if (tid < 128) b4 = *(const float4*)(Bm + (bn + lrA) * K + kn + lcA);
        }
#pragma unroll
        for (int kk = 0; kk < 8; kk++) {
            float4 x0 = *(const float4*)&As[kk][m0];
            float4 x1 = *(const float4*)&As[kk][m0 + 4];
            float4 y  = *(const float4*)&Bs[kk][n0];
            float am[8] = {x0.x, x0.y, x0.z, x0.w, x1.x, x1.y, x1.z, x1.w};
            float bb[4] = {y.x, y.y, y.z, y.w};
#pragma unroll
            for (int i = 0; i < 8; i++)
#pragma unroll
                for (int j = 0; j < 4; j++) acc[i][j] += am[i] * bb[j];
        }
        __syncthreads();
    }

    if (z == 0) {
#pragma unroll
        for (int i = 0; i < 8; i++) {
            float4 r = make_float4(acc[i][0], acc[i][1], acc[i][2], acc[i][3]);
            *(float4*)&g_wq[(bm + m0 + i) * MD + bn + n0] = r;
        }
    } else {
        float bb[4];
#pragma unroll
        for (int j = 0; j < 4; j++) bb[j] = bc[bn + n0 + j];
#pragma unroll
        for (int i = 0; i < 8; i++) {
            const int m = bm + m0 + i;
            const int b = m >> 9;
            const int s = m & 511;
#pragma unroll
            for (int j = 0; j < 4; j++)
                g_uht[b * (MD * SS) + (bn + n0 + j) * SS + s] = acc[i][j] + bb[j];
        }
    }
}

// ---------------------------------------------------------------------------
// align_kernel: grid (s-chunk, t-tile, b). One 128-s chunk x 16-t per block.
// Early-exits on fully-masked chunks. Writes RAW scores to pa.
// ---------------------------------------------------------------------------
__global__ __launch_bounds__(256) void align_kernel(
    const int* __restrict__ mem_masks, const float* __restrict__ v,
    float* __restrict__ pa)
{
    const int b = blockIdx.z;
    const int t0 = blockIdx.y * 16;
    const int c = blockIdx.x;
    const int len = mem_masks[b];
    if (c * 128 >= len) return;

    extern __shared__ float sh[];
    float* uh_sh = sh;                 // [256][128]
    float* wq_sh = sh + 256 * 128;     // [16][256]
    float* v_sh  = wq_sh + 16 * 256;   // [256]

    const int tid = threadIdx.x;
    const int lane = tid & 31;
    const int warp = tid >> 5;

    {
        const float* src = g_wq + (b * TT + t0) * MD;
        for (int i = tid; i < (16 * 256) / 4; i += 256)
            *(float4*)&wq_sh[i * 4] = *(const float4*)&src[i * 4];
        if (tid < 64)
            *(float4*)&v_sh[tid * 4] = *(const float4*)&v[tid * 4];
        const float* usrc = g_uht + b * (MD * SS) + c * 128;
        for (int i = tid; i < 256 * 32; i += 256) {
            const int d = i >> 5, g = i & 31;
            *(float4*)&uh_sh[d * 128 + g * 4] =
                *(const float4*)&usrc[d * SS + g * 4];
        }
    }
    __syncthreads();

    const int ta = warp * 2;
    const float* wq0 = wq_sh + ta * 256;
    const float* wq1 = wq0 + 256;
    const int sl = lane * 4;
    float4 a0 = make_float4(0.f, 0.f, 0.f, 0.f);
    float4 a1 = make_float4(0.f, 0.f, 0.f, 0.f);
#pragma unroll 4
    for (int d = 0; d < 256; d++) {
        float4 u = *(float4*)&uh_sh[d * 128 + sl];
        float w0 = wq0[d], w1 = wq1[d], vd = v_sh[d];
        a0.x += vd * tanhap(u.x + w0);
        a0.y += vd * tanhap(u.y + w0);
        a0.z += vd * tanhap(u.z + w0);
        a0.w += vd * tanhap(u.w + w0);
        a1.x += vd * tanhap(u.x + w1);
        a1.y += vd * tanhap(u.y + w1);
        a1.z += vd * tanhap(u.z + w1);
        a1.w += vd * tanhap(u.w + w1);
    }
    const int sg = c * 128 + sl;
    *(float4*)&pa[(b * TT + t0 + ta) * SS + sg] = a0;
    *(float4*)&pa[(b * TT + t0 + ta + 1) * SS + sg] = a1;
}

// ---------------------------------------------------------------------------
// softmax_kernel: warp per t-row, 8 rows/block, 256 blocks.
// ---------------------------------------------------------------------------
__global__ __launch_bounds__(256) void softmax_kernel(
    const int* __restrict__ mem_masks, float* __restrict__ pa)
{
    const int lane = threadIdx.x & 31;
    const int warp = threadIdx.x >> 5;
    const int row = blockIdx.x * 8 + warp;   // 0..2047
    const int b = row >> 9;
    const int len = mem_masks[b];
    float* prow = pa + row * SS;
    const float NEG = -CUDART_INF_F;

    float vals[16];
    float mx = NEG;
#pragma unroll
    for (int k = 0; k < 16; k++) {
        const int s = lane + k * 32;
        const float val = (s < len) ? prow[s] : NEG;
        vals[k] = val;
        mx = fmaxf(mx, val);
    }
#pragma unroll
    for (int o = 16; o; o >>= 1) mx = fmaxf(mx, __shfl_xor_sync(~0u, mx, o));
    float sum = 0.f;
#pragma unroll
    for (int k = 0; k < 16; k++) {
        const int s = lane + k * 32;
        const float e = (s < len) ? __expf(vals[k] - mx) : 0.f;
        vals[k] = e;
        sum += e;
    }
#pragma unroll
    for (int o = 16; o; o >>= 1) sum += __shfl_xor_sync(~0u, sum, o);
    const float inv = 1.0f / sum;
#pragma unroll
    for (int k = 0; k < 16; k++) prow[lane + k * 32] = vals[k] * inv;
}

// ---------------------------------------------------------------------------
// ctx_kernel: split-K=2 partials of c[t][m] = sum_s P[t][s]*mems[b][s][m].
// 64x64 tile, 256 thr, 4x4/thread. Grid (4,8,8)=256 blocks.
// ---------------------------------------------------------------------------
__global__ __launch_bounds__(256) void ctx_kernel(
    const float* __restrict__ mems, const int* __restrict__ mem_masks,
    const float* __restrict__ pa)
{
    __shared__ float As[8][68];   // [k][t]
    __shared__ float Bs[8][68];   // [k][m]

    const int b = blockIdx.z >> 1;
    const int kc = blockIdx.z & 1;
    const int t0 = blockIdx.y * 64;
    const int n0b = blockIdx.x * 64;
    const int len = mem_masks[b];
    const int s0 = kc * 256;
    int lc = len - s0;
    if (lc > 256) lc = 256;
    const int NT = (lc > 0) ? ((lc + 7) >> 3) : 0;

    const int tid = threadIdx.x;
    const int lr = tid >> 2;
    const int lk = (tid & 3) * 2;
    const int bk = tid >> 5;
    const int bm = (tid & 31) * 2;
    const int tx = tid & 15, ty = tid >> 4;
    const int n0 = tx * 4, m0 = ty * 4;

    float acc[4][4];
#pragma unroll
    for (int i = 0; i < 4; i++)
#pragma unroll
        for (int j = 0; j < 4; j++) acc[i][j] = 0.f;

    if (NT > 0) {
        const float* P  = pa + (b * TT + t0 + lr) * SS + s0 + lk;
        const float* Mb = mems + b * (SS * MD) + (s0 + bk) * MD + n0b + bm;

        float2 a2 = *(const float2*)P;
        float2 b2 = *(const float2*)Mb;

        for (int kt = 0; kt < NT; kt++) {
            As[lk][lr] = a2.x; As[lk + 1][lr] = a2.y;
            *(float2*)&Bs[bk][bm] = b2;
            __syncthreads();
            if (kt + 1 < NT) {
                a2 = *(const float2*)(P + (kt + 1) * 8);
                b2 = *(const float2*)(Mb + (kt + 1) * 8 * MD);
            }
#pragma unroll
            for (int k = 0; k < 8; k++) {
                float4 af = *(const float4*)&As[k][m0];
                float4 bf = *(const float4*)&Bs[k][n0];
                float am[4] = {af.x, af.y, af.z, af.w};
                float bb[4] = {bf.x, bf.y, bf.z, bf.w};
#pragma unroll
                for (int i = 0; i < 4; i++)
#pragma unroll
                    for (int j = 0; j < 4; j++) acc[i][j] += am[i] * bb[j];
            }
            __syncthreads();
        }
    }

    float* dst = g_ctxp[kc];
#pragma unroll
    for (int i = 0; i < 4; i++) {
        float4 r = make_float4(acc[i][0], acc[i][1], acc[i][2], acc[i][3]);
        *(float4*)&dst[(b * TT + t0 + m0 + i) * MD + n0b + n0] = r;
    }
}

// ---------------------------------------------------------------------------
// out_kernel: split-K partials of concat(c,inputs) @ Wout^T.
// kc = kc_base + blockIdx.z. kc=0 reads ctx as p0+p1 (folds ctx reduce);
// kc=1/2 read inputs halves (NO upstream deps -> run on side stream).
// 128x64 tile, 256 threads, 8x4.
// ---------------------------------------------------------------------------
__global__ __launch_bounds__(256) void out_kernel(
    const float* __restrict__ inputs, const float* __restrict__ Wout,
    int kc_base)
{
    __shared__ float As[8][132];
    __shared__ float Bs[8][68];

    const int tid = threadIdx.x;
    const int bm = blockIdx.y * 128;
    const int bn = blockIdx.x * 64;
    const int kc = kc_base + blockIdx.z;
    const int lrA = tid >> 1;
    const int lcA = (tid & 1) * 4;
    const int tx = tid & 15, ty = tid >> 4;
    const int n0 = tx * 4, m0 = ty * 8;

    const float* p0row = g_ctxp[0] + (bm + lrA) * MD;
    const float* p1row = g_ctxp[1] + (bm + lrA) * MD;
    const float* irow  = inputs + (bm + lrA) * IND + (kc - 1) * 256;
    const float* Wbase = Wout + (bn + lrA) * 768 + kc * 256;

    auto fetchA = [&](int k0) -> float4 {
        if (kc == 0) {
            float4 x = *(const float4*)(p0row + k0 + lcA);
            float4 y = *(const float4*)(p1row + k0 + lcA);
            return make_float4(x.x + y.x, x.y + y.y, x.z + y.z, x.w + y.w);
        }
        return *(const float4*)(irow + k0 + lcA);
    };

    float acc[8][4];
#pragma unroll
    for (int i = 0; i < 8; i++)
#pragma unroll
        for (int j = 0; j < 4; j++) acc[i][j] = 0.f;

    float4 a4 = fetchA(0);
    float4 b4 = make_float4(0.f, 0.f, 0.f, 0.f);
    if (tid < 128) b4 = *(const float4*)(Wbase + lcA);

    for (int k0 = 0; k0 < 256; k0 += 8) {
        As[lcA + 0][lrA] = a4.x; As[lcA + 1][lrA] = a4.y;
        As[lcA + 2][lrA] = a4.z; As[lcA + 3][lrA] = a4.w;
        if (tid < 128) {
            Bs[lcA + 0][lrA] = b4.x; Bs[lcA + 1][lrA] = b4.y;
            Bs[lcA + 2][lrA] = b4.z; Bs[lcA + 3][lrA] = b4.w;
        }
        __syncthreads();
        const int kn = k0 + 8;
        if (kn < 256) {
            a4 = fetchA(kn);
            if (tid < 128) b4 = *(const float4*)(Wbase + kn + lcA);
        }
#pragma unroll
        for (int kk = 0; kk < 8; kk++) {
            float4 x0 = *(const float4*)&As[kk][m0];
            float4 x1 = *(const float4*)&As[kk][m0 + 4];
            float4 y  = *(const float4*)&Bs[kk][n0];
            float am[8] = {x0.x, x0.y, x0.z, x0.w, x1.x, x1.y, x1.z, x1.w};
            float bb[4] = {y.x, y.y, y.z, y.w};
#pragma unroll
            for (int i = 0; i < 8; i++)
#pragma unroll
                for (int j = 0; j < 4; j++) acc[i][j] += am[i] * bb[j];
        }
        __syncthreads();
    }

    float* dst = g_outp[kc];
#pragma unroll
    for (int i = 0; i < 8; i++) {
        float4 r = make_float4(acc[i][0], acc[i][1], acc[i][2], acc[i][3]);
        *(float4*)&dst[(bm + m0 + i) * IND + bn + n0] = r;
    }
}

// ---------------------------------------------------------------------------
// reduce_kernel: out = outp0 + outp1 + outp2 + bias
// ---------------------------------------------------------------------------
__global__ __launch_bounds__(256) void reduce_kernel(
    const float* __restrict__ bout, float* __restrict__ out)
{
    const int idx = blockIdx.x * 256 + threadIdx.x;   // float4 index
    const int e = idx * 4;
    float4 p0 = *(const float4*)&g_outp[0][e];
    float4 p1 = *(const float4*)&g_outp[1][e];
    float4 p2 = *(const float4*)&g_outp[2][e];
    float4 bb = *(const float4*)&bout[e & 511];
    float4 r = make_float4(p0.x + p1.x + p2.x + bb.x,
                           p0.y + p1.y + p2.y + bb.y,
                           p0.z + p1.z + p2.z + bb.z,
                           p0.w + p1.w + p2.w + bb.w);
    *(float4*)&out[e] = r;
}

// ---------------------------------------------------------------------------
extern "C" void kernel_launch(void* const* d_in, const int* in_sizes, int n_in,
                              void* d_out, int out_size)
{
    const float* inputs    = (const float*)d_in[0];
    const float* mems      = (const float*)d_in[1];
    const int*   mem_masks = (const int*)d_in[2];
    const float* Wq        = (const float*)d_in[3];
    const float* Wc        = (const float*)d_in[4];
    const float* bc        = (const float*)d_in[5];
    const float* v         = (const float*)d_in[6];
    const float* Wout      = (const float*)d_in[7];
    const float* bout      = (const float*)d_in[8];

    float* out = (float*)d_out;
    float* pa;
    if (out_size >= BN * TT * IND + BN * TT * SS) {
        pa = out + BN * TT * IND;  // align written in-place in the output
    } else {
        cudaGetSymbolAddress((void**)&pa, g_align_scratch);
    }

    const size_t SMEM_ALIGN = (size_t)(256 * 128 + 16 * 256 + 256) * sizeof(float);
    cudaFuncSetAttribute(align_kernel,
                         cudaFuncAttributeMaxDynamicSharedMemorySize, (int)SMEM_ALIGN);

    // One-time resource creation (host-side objects only; identical work
    // is enqueued on every call, so determinism is preserved).
    static cudaStream_t s2 = nullptr;
    static cudaEvent_t evFork = nullptr, evJoin = nullptr;
    if (s2 == nullptr) {
        cudaStreamCreateWithFlags(&s2, cudaStreamNonBlocking);
        cudaEventCreateWithFlags(&evFork, cudaEventDisableTiming);
        cudaEventCreateWithFlags(&evJoin, cudaEventDisableTiming);
    }

    // Fork: out partials kc=1,2 depend only on inputs/Wout -> side stream,
    // overlapping the entire proj->align->softmax->ctx chain.
    cudaEventRecord(evFork, 0);
    cudaStreamWaitEvent(s2, evFork, 0);
    out_kernel<<<dim3(8, 16, 2), 256, 0, s2>>>(inputs, Wout, 1);
    cudaEventRecord(evJoin, s2);

    // Critical path on the main stream.
    proj_kernel<<<dim3(4, 16, 2), 256>>>(inputs, mems, Wq, Wc, bc);
    align_kernel<<<dim3(4, 32, 4), 256, SMEM_ALIGN>>>(mem_masks, v, pa);
    softmax_kernel<<<256, 256>>>(mem_masks, pa);
    ctx_kernel<<<dim3(4, 8, 8), 256>>>(mems, mem_masks, pa);
    out_kernel<<<dim3(8, 16, 1), 256>>>(inputs, Wout, 0);

    // Join, then final reduce.
    cudaStreamWaitEvent(0, evJoin, 0);
    reduce_kernel<<<(BN * TT * IND) / (256 * 4), 256>>>(bout, out);
}

// round 8
// speedup vs baseline: 1.0524x; 1.0524x over previous
#include <cuda_runtime.h>
#include <math_constants.h>

#define BN 4
#define TT 512
#define SS 512
#define IND 512
#define MD 256

// Scratch (allocation-free rule: __device__ globals)
__device__ float g_wqp[2][BN * TT * MD];        // wq split-K partials
__device__ float g_uht[BN * MD * SS];           // [b][d][s]  (transposed uh)
__device__ float g_ctxp[2][BN * TT * MD];       // ctx split-K partials
__device__ float g_outp[3][BN * TT * IND];      // out split-K partials
__device__ float g_align_scratch[BN * TT * SS];

__device__ __forceinline__ float tanhap(float x) {
    float y;
    asm("tanh.approx.f32 %0, %1;" : "=f"(y) : "f"(x));
    return y;
}

// ---------------------------------------------------------------------------
// proj_kernel: 3 balanced K=256 jobs, grid (4,16,3)=192 blocks.
//   z=0: g_wqp[0] = inputs[:, 0:256]   @ Wq[:, 0:256]^T
//   z=1: g_wqp[1] = inputs[:, 256:512] @ Wq[:, 256:512]^T
//   z=2: g_uht[b][n][s] = mems @ Wc^T + bc (transposed store)
// 128x64 block tile, 256 threads, 8x4 per thread, TK=8, register prefetch.
// ---------------------------------------------------------------------------
__global__ __launch_bounds__(256) void proj_kernel(
    const float* __restrict__ inputs, const float* __restrict__ mems,
    const float* __restrict__ Wq, const float* __restrict__ Wc,
    const float* __restrict__ bc)
{
    const int z = blockIdx.z;
    const bool is_uht = (z == 2);
    const int rowstride = is_uht ? MD : IND;     // A row stride
    const int koff = is_uht ? 0 : z * 256;       // K chunk offset
    const float* A  = is_uht ? mems : inputs;
    const float* Bm = is_uht ? Wc : Wq;

    __shared__ float As[8][132];
    __shared__ float Bs[8][68];

    const int tid = threadIdx.x;
    const int bm = blockIdx.y * 128;
    const int bn = blockIdx.x * 64;
    const int lrA = tid >> 1;
    const int lcA = (tid & 1) * 4;
    const int tx = tid & 15, ty = tid >> 4;
    const int n0 = tx * 4, m0 = ty * 8;

    const float* Arow = A + (bm + lrA) * rowstride + koff + lcA;
    const float* Wrow = Bm + (bn + lrA) * rowstride + koff + lcA;

    float acc[8][4];
#pragma unroll
    for (int i = 0; i < 8; i++)
#pragma unroll
        for (int j = 0; j < 4; j++) acc[i][j] = 0.f;

    float4 a4 = *(const float4*)Arow;
    float4 b4 = make_float4(0.f, 0.f, 0.f, 0.f);
    if (tid < 128) b4 = *(const float4*)Wrow;

    for (int k0 = 0; k0 < 256; k0 += 8) {
        As[lcA + 0][lrA] = a4.x; As[lcA + 1][lrA] = a4.y;
        As[lcA + 2][lrA] = a4.z; As[lcA + 3][lrA] = a4.w;
        if (tid < 128) {
            Bs[lcA + 0][lrA] = b4.x; Bs[lcA + 1][lrA] = b4.y;
            Bs[lcA + 2][lrA] = b4.z; Bs[lcA + 3][lrA] = b4.w;
        }
        __syncthreads();
        const int kn = k0 + 8;
        if (kn < 256) {
            a4 = *(const float4*)(Arow + kn);
            if (tid < 128) b4 = *(const float4*)(Wrow + kn);
        }
#pragma unroll
        for (int kk = 0; kk < 8; kk++) {
            float4 x0 = *(const float4*)&As[kk][m0];
            float4 x1 = *(const float4*)&As[kk][m0 + 4];
            float4 y  = *(const float4*)&Bs[kk][n0];
            float am[8] = {x0.x, x0.y, x0.z, x0.w, x1.x, x1.y, x1.z, x1.w};
            float bb[4] = {y.x, y.y, y.z, y.w};
#pragma unroll
            for (int i = 0; i < 8; i++)
#pragma unroll
                for (int j = 0; j < 4; j++) acc[i][j] += am[i] * bb[j];
        }
        __syncthreads();
    }

    if (!is_uht) {
        float* dst = g_wqp[z];
#pragma unroll
        for (int i = 0; i < 8; i++) {
            float4 r = make_float4(acc[i][0], acc[i][1], acc[i][2], acc[i][3]);
            *(float4*)&dst[(bm + m0 + i) * MD + bn + n0] = r;
        }
    } else {
        float bb[4];
#pragma unroll
        for (int j = 0; j < 4; j++) bb[j] = bc[bn + n0 + j];
#pragma unroll
        for (int i = 0; i < 8; i++) {
            const int m = bm + m0 + i;
            const int b = m >> 9;
            const int s = m & 511;
#pragma unroll
            for (int j = 0; j < 4; j++)
                g_uht[b * (MD * SS) + (bn + n0 + j) * SS + s] = acc[i][j] + bb[j];
        }
    }
}

// ---------------------------------------------------------------------------
// align_kernel: grid (s-chunk, t-tile, b). One 128-s chunk x 16-t per block.
// Early-exits on fully-masked chunks. wq tile = wqp0 + wqp1 (folds the
// proj split-K reduce). Writes RAW scores to pa.
// ---------------------------------------------------------------------------
__global__ __launch_bounds__(256) void align_kernel(
    const int* __restrict__ mem_masks, const float* __restrict__ v,
    float* __restrict__ pa)
{
    const int b = blockIdx.z;
    const int t0 = blockIdx.y * 16;
    const int c = blockIdx.x;
    const int len = mem_masks[b];
    if (c * 128 >= len) return;

    extern __shared__ float sh[];
    float* uh_sh = sh;                 // [256][128]
    float* wq_sh = sh + 256 * 128;     // [16][256]
    float* v_sh  = wq_sh + 16 * 256;   // [256]

    const int tid = threadIdx.x;
    const int lane = tid & 31;
    const int warp = tid >> 5;

    {
        const float* s0p = g_wqp[0] + (b * TT + t0) * MD;
        const float* s1p = g_wqp[1] + (b * TT + t0) * MD;
        for (int i = tid; i < (16 * 256) / 4; i += 256) {
            float4 x = *(const float4*)&s0p[i * 4];
            float4 y = *(const float4*)&s1p[i * 4];
            float4 r = make_float4(x.x + y.x, x.y + y.y, x.z + y.z, x.w + y.w);
            *(float4*)&wq_sh[i * 4] = r;
        }
        if (tid < 64)
            *(float4*)&v_sh[tid * 4] = *(const float4*)&v[tid * 4];
        const float* usrc = g_uht + b * (MD * SS) + c * 128;
        for (int i = tid; i < 256 * 32; i += 256) {
            const int d = i >> 5, g = i & 31;
            *(float4*)&uh_sh[d * 128 + g * 4] =
                *(const float4*)&usrc[d * SS + g * 4];
        }
    }
    __syncthreads();

    const int ta = warp * 2;
    const float* wq0 = wq_sh + ta * 256;
    const float* wq1 = wq0 + 256;
    const int sl = lane * 4;
    float4 a0 = make_float4(0.f, 0.f, 0.f, 0.f);
    float4 a1 = make_float4(0.f, 0.f, 0.f, 0.f);
#pragma unroll 4
    for (int d = 0; d < 256; d++) {
        float4 u = *(float4*)&uh_sh[d * 128 + sl];
        float w0 = wq0[d], w1 = wq1[d], vd = v_sh[d];
        a0.x += vd * tanhap(u.x + w0);
        a0.y += vd * tanhap(u.y + w0);
        a0.z += vd * tanhap(u.z + w0);
        a0.w += vd * tanhap(u.w + w0);
        a1.x += vd * tanhap(u.x + w1);
        a1.y += vd * tanhap(u.y + w1);
        a1.z += vd * tanhap(u.z + w1);
        a1.w += vd * tanhap(u.w + w1);
    }
    const int sg = c * 128 + sl;
    *(float4*)&pa[(b * TT + t0 + ta) * SS + sg] = a0;
    *(float4*)&pa[(b * TT + t0 + ta + 1) * SS + sg] = a1;
}

// ---------------------------------------------------------------------------
// softmax_kernel: warp per t-row, 8 rows/block, 256 blocks.
// ---------------------------------------------------------------------------
__global__ __launch_bounds__(256) void softmax_kernel(
    const int* __restrict__ mem_masks, float* __restrict__ pa)
{
    const int lane = threadIdx.x & 31;
    const int warp = threadIdx.x >> 5;
    const int row = blockIdx.x * 8 + warp;   // 0..2047
    const int b = row >> 9;
    const int len = mem_masks[b];
    float* prow = pa + row * SS;
    const float NEG = -CUDART_INF_F;

    float vals[16];
    float mx = NEG;
#pragma unroll
    for (int k = 0; k < 16; k++) {
        const int s = lane + k * 32;
        const float val = (s < len) ? prow[s] : NEG;
        vals[k] = val;
        mx = fmaxf(mx, val);
    }
#pragma unroll
    for (int o = 16; o; o >>= 1) mx = fmaxf(mx, __shfl_xor_sync(~0u, mx, o));
    float sum = 0.f;
#pragma unroll
    for (int k = 0; k < 16; k++) {
        const int s = lane + k * 32;
        const float e = (s < len) ? __expf(vals[k] - mx) : 0.f;
        vals[k] = e;
        sum += e;
    }
#pragma unroll
    for (int o = 16; o; o >>= 1) sum += __shfl_xor_sync(~0u, sum, o);
    const float inv = 1.0f / sum;
#pragma unroll
    for (int k = 0; k < 16; k++) prow[lane + k * 32] = vals[k] * inv;
}

// ---------------------------------------------------------------------------
// ctx_kernel: split-K=2 partials of c[t][m] = sum_s P[t][s]*mems[b][s][m].
// 64x64 tile, 256 thr, 4x4/thread. Grid (4,8,8)=256 blocks.
// ---------------------------------------------------------------------------
__global__ __launch_bounds__(256) void ctx_kernel(
    const float* __restrict__ mems, const int* __restrict__ mem_masks,
    const float* __restrict__ pa)
{
    __shared__ float As[8][68];   // [k][t]
    __shared__ float Bs[8][68];   // [k][m]

    const int b = blockIdx.z >> 1;
    const int kc = blockIdx.z & 1;
    const int t0 = blockIdx.y * 64;
    const int n0b = blockIdx.x * 64;
    const int len = mem_masks[b];
    const int s0 = kc * 256;
    int lc = len - s0;
    if (lc > 256) lc = 256;
    const int NT = (lc > 0) ? ((lc + 7) >> 3) : 0;

    const int tid = threadIdx.x;
    const int lr = tid >> 2;
    const int lk = (tid & 3) * 2;
    const int bk = tid >> 5;
    const int bm = (tid & 31) * 2;
    const int tx = tid & 15, ty = tid >> 4;
    const int n0 = tx * 4, m0 = ty * 4;

    float acc[4][4];
#pragma unroll
    for (int i = 0; i < 4; i++)
#pragma unroll
        for (int j = 0; j < 4; j++) acc[i][j] = 0.f;

    if (NT > 0) {
        const float* P  = pa + (b * TT + t0 + lr) * SS + s0 + lk;
        const float* Mb = mems + b * (SS * MD) + (s0 + bk) * MD + n0b + bm;

        float2 a2 = *(const float2*)P;
        float2 b2 = *(const float2*)Mb;

        for (int kt = 0; kt < NT; kt++) {
            As[lk][lr] = a2.x; As[lk + 1][lr] = a2.y;
            *(float2*)&Bs[bk][bm] = b2;
            __syncthreads();
            if (kt + 1 < NT) {
                a2 = *(const float2*)(P + (kt + 1) * 8);
                b2 = *(const float2*)(Mb + (kt + 1) * 8 * MD);
            }
#pragma unroll
            for (int k = 0; k < 8; k++) {
                float4 af = *(const float4*)&As[k][m0];
                float4 bf = *(const float4*)&Bs[k][n0];
                float am[4] = {af.x, af.y, af.z, af.w};
                float bb[4] = {bf.x, bf.y, bf.z, bf.w};
#pragma unroll
                for (int i = 0; i < 4; i++)
#pragma unroll
                    for (int j = 0; j < 4; j++) acc[i][j] += am[i] * bb[j];
            }
            __syncthreads();
        }
    }

    float* dst = g_ctxp[kc];
#pragma unroll
    for (int i = 0; i < 4; i++) {
        float4 r = make_float4(acc[i][0], acc[i][1], acc[i][2], acc[i][3]);
        *(float4*)&dst[(b * TT + t0 + m0 + i) * MD + n0b + n0] = r;
    }
}

// ---------------------------------------------------------------------------
// out_kernel: split-K=3 partials of concat(c,inputs) @ Wout^T.
// kc=0 reads ctx as p0+p1 (folds ctx reduce); kc=1/2 read inputs halves.
// 128x64 tile, 256 threads, 8x4. Grid (8,16,3)=384 blocks.
// ---------------------------------------------------------------------------
__global__ __launch_bounds__(256) void out_kernel(
    const float* __restrict__ inputs, const float* __restrict__ Wout)
{
    __shared__ float As[8][132];
    __shared__ float Bs[8][68];

    const int tid = threadIdx.x;
    const int bm = blockIdx.y * 128;
    const int bn = blockIdx.x * 64;
    const int kc = blockIdx.z;
    const int lrA = tid >> 1;
    const int lcA = (tid & 1) * 4;
    const int tx = tid & 15, ty = tid >> 4;
    const int n0 = tx * 4, m0 = ty * 8;

    const float* p0row = g_ctxp[0] + (bm + lrA) * MD;
    const float* p1row = g_ctxp[1] + (bm + lrA) * MD;
    const float* irow  = inputs + (bm + lrA) * IND + (kc - 1) * 256;
    const float* Wbase = Wout + (bn + lrA) * 768 + kc * 256;

    auto fetchA = [&](int k0) -> float4 {
        if (kc == 0) {
            float4 x = *(const float4*)(p0row + k0 + lcA);
            float4 y = *(const float4*)(p1row + k0 + lcA);
            return make_float4(x.x + y.x, x.y + y.y, x.z + y.z, x.w + y.w);
        }
        return *(const float4*)(irow + k0 + lcA);
    };

    float acc[8][4];
#pragma unroll
    for (int i = 0; i < 8; i++)
#pragma unroll
        for (int j = 0; j < 4; j++) acc[i][j] = 0.f;

    float4 a4 = fetchA(0);
    float4 b4 = make_float4(0.f, 0.f, 0.f, 0.f);
    if (tid < 128) b4 = *(const float4*)(Wbase + lcA);

    for (int k0 = 0; k0 < 256; k0 += 8) {
        As[lcA + 0][lrA] = a4.x; As[lcA + 1][lrA] = a4.y;
        As[lcA + 2][lrA] = a4.z; As[lcA + 3][lrA] = a4.w;
        if (tid < 128) {
            Bs[lcA + 0][lrA] = b4.x; Bs[lcA + 1][lrA] = b4.y;
            Bs[lcA + 2][lrA] = b4.z; Bs[lcA + 3][lrA] = b4.w;
        }
        __syncthreads();
        const int kn = k0 + 8;
        if (kn < 256) {
            a4 = fetchA(kn);
            if (tid < 128) b4 = *(const float4*)(Wbase + kn + lcA);
        }
#pragma unroll
        for (int kk = 0; kk < 8; kk++) {
            float4 x0 = *(const float4*)&As[kk][m0];
            float4 x1 = *(const float4*)&As[kk][m0 + 4];
            float4 y  = *(const float4*)&Bs[kk][n0];
            float am[8] = {x0.x, x0.y, x0.z, x0.w, x1.x, x1.y, x1.z, x1.w};
            float bb[4] = {y.x, y.y, y.z, y.w};
#pragma unroll
            for (int i = 0; i < 8; i++)
#pragma unroll
                for (int j = 0; j < 4; j++) acc[i][j] += am[i] * bb[j];
        }
        __syncthreads();
    }

    float* dst = g_outp[kc];
#pragma unroll
    for (int i = 0; i < 8; i++) {
        float4 r = make_float4(acc[i][0], acc[i][1], acc[i][2], acc[i][3]);
        *(float4*)&dst[(bm + m0 + i) * IND + bn + n0] = r;
    }
}

// ---------------------------------------------------------------------------
// reduce_kernel: out = outp0 + outp1 + outp2 + bias
// ---------------------------------------------------------------------------
__global__ __launch_bounds__(256) void reduce_kernel(
    const float* __restrict__ bout, float* __restrict__ out)
{
    const int idx = blockIdx.x * 256 + threadIdx.x;   // float4 index
    const int e = idx * 4;
    float4 p0 = *(const float4*)&g_outp[0][e];
    float4 p1 = *(const float4*)&g_outp[1][e];
    float4 p2 = *(const float4*)&g_outp[2][e];
    float4 bb = *(const float4*)&bout[e & 511];
    float4 r = make_float4(p0.x + p1.x + p2.x + bb.x,
                           p0.y + p1.y + p2.y + bb.y,
                           p0.z + p1.z + p2.z + bb.z,
                           p0.w + p1.w + p2.w + bb.w);
    *(float4*)&out[e] = r;
}

// ---------------------------------------------------------------------------
extern "C" void kernel_launch(void* const* d_in, const int* in_sizes, int n_in,
                              void* d_out, int out_size)
{
    const float* inputs    = (const float*)d_in[0];
    const float* mems      = (const float*)d_in[1];
    const int*   mem_masks = (const int*)d_in[2];
    const float* Wq        = (const float*)d_in[3];
    const float* Wc        = (const float*)d_in[4];
    const float* bc        = (const float*)d_in[5];
    const float* v         = (const float*)d_in[6];
    const float* Wout      = (const float*)d_in[7];
    const float* bout      = (const float*)d_in[8];

    float* out = (float*)d_out;
    float* pa;
    if (out_size >= BN * TT * IND + BN * TT * SS) {
        pa = out + BN * TT * IND;  // align written in-place in the output
    } else {
        cudaGetSymbolAddress((void**)&pa, g_align_scratch);
    }

    const size_t SMEM_ALIGN = (size_t)(256 * 128 + 16 * 256 + 256) * sizeof(float);
    cudaFuncSetAttribute(align_kernel,
                         cudaFuncAttributeMaxDynamicSharedMemorySize, (int)SMEM_ALIGN);

    proj_kernel<<<dim3(4, 16, 3), 256>>>(inputs, mems, Wq, Wc, bc);
    align_kernel<<<dim3(4, 32, 4), 256, SMEM_ALIGN>>>(mem_masks, v, pa);
    softmax_kernel<<<256, 256>>>(mem_masks, pa);
    ctx_kernel<<<dim3(4, 8, 8), 256>>>(mems, mem_masks, pa);
    out_kernel<<<dim3(8, 16, 3), 256>>>(inputs, Wout);
    reduce_kernel<<<(BN * TT * IND) / (256 * 4), 256>>>(bout, out);
}

// round 10
// speedup vs baseline: 1.2298x; 1.1685x over previous
#include <cuda_runtime.h>
#include <math_constants.h>

#define BN 4
#define TT 512
#define SS 512
#define IND 512
#define MD 256

// Scratch (allocation-free rule: __device__ globals)
__device__ float g_wq[BN * TT * MD];            // [b*T+t][d]
__device__ float g_uht[BN * MD * SS];           // [b][d][s]  (transposed uh)
__device__ float g_ctxp[2][BN * TT * MD];       // ctx split-K partials
__device__ float g_outp[3][BN * TT * IND];      // out split-K partials
__device__ float g_align_scratch[BN * TT * SS];

__device__ __forceinline__ float tanhap(float x) {
    float y;
    asm("tanh.approx.f32 %0, %1;" : "=f"(y) : "f"(x));
    return y;
}

// ---------------------------------------------------------------------------
// proj_kernel (R6): z=0 -> g_wq = inputs @ Wq^T   (K=512)
//                   z=1 -> g_uht[b][n][s] = mems @ Wc^T + bc (transposed)
// 128x64 block tile, 256 threads, 8x4 per thread, TK=8, register prefetch.
// ---------------------------------------------------------------------------
__global__ __launch_bounds__(256) void proj_kernel(
    const float* __restrict__ inputs, const float* __restrict__ mems,
    const float* __restrict__ Wq, const float* __restrict__ Wc,
    const float* __restrict__ bc)
{
    const int z = blockIdx.z;
    const float* A  = z ? mems : inputs;
    const float* Bm = z ? Wc : Wq;
    const int K = z ? MD : IND;

    __shared__ float As[8][132];
    __shared__ float Bs[8][68];

    const int tid = threadIdx.x;
    const int bm = blockIdx.y * 128;
    const int bn = blockIdx.x * 64;
    const int lrA = tid >> 1;
    const int lcA = (tid & 1) * 4;
    const int tx = tid & 15, ty = tid >> 4;
    const int n0 = tx * 4, m0 = ty * 8;

    float acc[8][4];
#pragma unroll
    for (int i = 0; i < 8; i++)
#pragma unroll
        for (int j = 0; j < 4; j++) acc[i][j] = 0.f;

    float4 a4 = *(const float4*)(A + (bm + lrA) * K + lcA);
    float4 b4 = make_float4(0.f, 0.f, 0.f, 0.f);
    if (tid < 128) b4 = *(const float4*)(Bm + (bn + lrA) * K + lcA);

    for (int k0 = 0; k0 < K; k0 += 8) {
        As[lcA + 0][lrA] = a4.x; As[lcA + 1][lrA] = a4.y;
        As[lcA + 2][lrA] = a4.z; As[lcA + 3][lrA] = a4.w;
        if (tid < 128) {
            Bs[lcA + 0][lrA] = b4.x; Bs[lcA + 1][lrA] = b4.y;
            Bs[lcA + 2][lrA] = b4.z; Bs[lcA + 3][lrA] = b4.w;
        }
        __syncthreads();
        const int kn = k0 + 8;
        if (kn < K) {
            a4 = *(const float4*)(A + (bm + lrA) * K + kn + lcA);
            if (tid < 128) b4 = *(const float4*)(Bm + (bn + lrA) * K + kn + lcA);
        }
#pragma unroll
        for (int kk = 0; kk < 8; kk++) {
            float4 x0 = *(const float4*)&As[kk][m0];
            float4 x1 = *(const float4*)&As[kk][m0 + 4];
            float4 y  = *(const float4*)&Bs[kk][n0];
            float am[8] = {x0.x, x0.y, x0.z, x0.w, x1.x, x1.y, x1.z, x1.w};
            float bb[4] = {y.x, y.y, y.z, y.w};
#pragma unroll
            for (int i = 0; i < 8; i++)
#pragma unroll
                for (int j = 0; j < 4; j++) acc[i][j] += am[i] * bb[j];
        }
        __syncthreads();
    }

    if (z == 0) {
#pragma unroll
        for (int i = 0; i < 8; i++) {
            float4 r = make_float4(acc[i][0], acc[i][1], acc[i][2], acc[i][3]);
            *(float4*)&g_wq[(bm + m0 + i) * MD + bn + n0] = r;
        }
    } else {
        float bb[4];
#pragma unroll
        for (int j = 0; j < 4; j++) bb[j] = bc[bn + n0 + j];
#pragma unroll
        for (int i = 0; i < 8; i++) {
            const int m = bm + m0 + i;
            const int b = m >> 9;
            const int s = m & 511;
#pragma unroll
            for (int j = 0; j < 4; j++)
                g_uht[b * (MD * SS) + (bn + n0 + j) * SS + s] = acc[i][j] + bb[j];
        }
    }
}

// ---------------------------------------------------------------------------
// align_kernel: 64-s chunks (was 128) -> smaller work items, 2 blocks/SM
// residency (smem 82KB), shallower waves, less tail quantization.
// Grid (8 s-chunks, 32 t-tiles, b). Early-exit on masked chunks.
// Warp = 2 t-rows x 64 s (2 s per lane, float2). Writes RAW scores.
// ---------------------------------------------------------------------------
__global__ __launch_bounds__(256) void align_kernel(
    const int* __restrict__ mem_masks, const float* __restrict__ v,
    float* __restrict__ pa)
{
    const int b = blockIdx.z;
    const int t0 = blockIdx.y * 16;
    const int c = blockIdx.x;
    const int len = mem_masks[b];
    if (c * 64 >= len) return;

    extern __shared__ float sh[];
    float* uh_sh = sh;                 // [256 d][64 s]
    float* wq_sh = sh + 256 * 64;      // [16][256]
    float* v_sh  = wq_sh + 16 * 256;   // [256]

    const int tid = threadIdx.x;
    const int lane = tid & 31;
    const int warp = tid >> 5;

    {
        const float* src = g_wq + (b * TT + t0) * MD;
        for (int i = tid; i < (16 * 256) / 4; i += 256)
            *(float4*)&wq_sh[i * 4] = *(const float4*)&src[i * 4];
        if (tid < 64)
            *(float4*)&v_sh[tid * 4] = *(const float4*)&v[tid * 4];
        // uh chunk: [256 d][64 s]; 16 float4 per d row
        const float* usrc = g_uht + b * (MD * SS) + c * 64;
        for (int i = tid; i < 256 * 16; i += 256) {
            const int d = i >> 4, g = i & 15;
            *(float4*)&uh_sh[d * 64 + g * 4] =
                *(const float4*)&usrc[d * SS + g * 4];
        }
    }
    __syncthreads();

    // warp handles t rows {2w, 2w+1}; lane handles s pair lane*2
    const int ta = warp * 2;
    const float* wq0 = wq_sh + ta * 256;
    const float* wq1 = wq0 + 256;
    const int sl = lane * 2;
    float2 a0 = make_float2(0.f, 0.f);
    float2 a1 = make_float2(0.f, 0.f);
#pragma unroll 8
    for (int d = 0; d < 256; d++) {
        float2 u = *(float2*)&uh_sh[d * 64 + sl];
        float w0 = wq0[d], w1 = wq1[d], vd = v_sh[d];
        a0.x += vd * tanhap(u.x + w0);
        a0.y += vd * tanhap(u.y + w0);
        a1.x += vd * tanhap(u.x + w1);
        a1.y += vd * tanhap(u.y + w1);
    }
    const int sg = c * 64 + sl;
    *(float2*)&pa[(b * TT + t0 + ta) * SS + sg] = a0;
    *(float2*)&pa[(b * TT + t0 + ta + 1) * SS + sg] = a1;
}

// ---------------------------------------------------------------------------
// softmax_kernel: warp per t-row, 8 rows/block, 256 blocks.
// ---------------------------------------------------------------------------
__global__ __launch_bounds__(256) void softmax_kernel(
    const int* __restrict__ mem_masks, float* __restrict__ pa)
{
    const int lane = threadIdx.x & 31;
    const int warp = threadIdx.x >> 5;
    const int row = blockIdx.x * 8 + warp;   // 0..2047
    const int b = row >> 9;
    const int len = mem_masks[b];
    float* prow = pa + row * SS;
    const float NEG = -CUDART_INF_F;

    float vals[16];
    float mx = NEG;
#pragma unroll
    for (int k = 0; k < 16; k++) {
        const int s = lane + k * 32;
        const float val = (s < len) ? prow[s] : NEG;
        vals[k] = val;
        mx = fmaxf(mx, val);
    }
#pragma unroll
    for (int o = 16; o; o >>= 1) mx = fmaxf(mx, __shfl_xor_sync(~0u, mx, o));
    float sum = 0.f;
#pragma unroll
    for (int k = 0; k < 16; k++) {
        const int s = lane + k * 32;
        const float e = (s < len) ? __expf(vals[k] - mx) : 0.f;
        vals[k] = e;
        sum += e;
    }
#pragma unroll
    for (int o = 16; o; o >>= 1) sum += __shfl_xor_sync(~0u, sum, o);
    const float inv = 1.0f / sum;
#pragma unroll
    for (int k = 0; k < 16; k++) prow[lane + k * 32] = vals[k] * inv;
}

// ---------------------------------------------------------------------------
// ctx_kernel: split-K=2 partials of c[t][m] = sum_s P[t][s]*mems[b][s][m].
// 64x64 tile, 256 thr, 4x4/thread. Grid (4,8,8)=256 blocks.
// ---------------------------------------------------------------------------
__global__ __launch_bounds__(256) void ctx_kernel(
    const float* __restrict__ mems, const int* __restrict__ mem_masks,
    const float* __restrict__ pa)
{
    __shared__ float As[8][68];   // [k][t]
    __shared__ float Bs[8][68];   // [k][m]

    const int b = blockIdx.z >> 1;
    const int kc = blockIdx.z & 1;
    const int t0 = blockIdx.y * 64;
    const int n0b = blockIdx.x * 64;
    const int len = mem_masks[b];
    const int s0 = kc * 256;
    int lc = len - s0;
    if (lc > 256) lc = 256;
    const int NT = (lc > 0) ? ((lc + 7) >> 3) : 0;

    const int tid = threadIdx.x;
    const int lr = tid >> 2;
    const int lk = (tid & 3) * 2;
    const int bk = tid >> 5;
    const int bm = (tid & 31) * 2;
    const int tx = tid & 15, ty = tid >> 4;
    const int n0 = tx * 4, m0 = ty * 4;

    float acc[4][4];
#pragma unroll
    for (int i = 0; i < 4; i++)
#pragma unroll
        for (int j = 0; j < 4; j++) acc[i][j] = 0.f;

    if (NT > 0) {
        const float* P  = pa + (b * TT + t0 + lr) * SS + s0 + lk;
        const float* Mb = mems + b * (SS * MD) + (s0 + bk) * MD + n0b + bm;

        float2 a2 = *(const float2*)P;
        float2 b2 = *(const float2*)Mb;

        for (int kt = 0; kt < NT; kt++) {
            As[lk][lr] = a2.x; As[lk + 1][lr] = a2.y;
            *(float2*)&Bs[bk][bm] = b2;
            __syncthreads();
            if (kt + 1 < NT) {
                a2 = *(const float2*)(P + (kt + 1) * 8);
                b2 = *(const float2*)(Mb + (kt + 1) * 8 * MD);
            }
#pragma unroll
            for (int k = 0; k < 8; k++) {
                float4 af = *(const float4*)&As[k][m0];
                float4 bf = *(const float4*)&Bs[k][n0];
                float am[4] = {af.x, af.y, af.z, af.w};
                float bb[4] = {bf.x, bf.y, bf.z, bf.w};
#pragma unroll
                for (int i = 0; i < 4; i++)
#pragma unroll
                    for (int j = 0; j < 4; j++) acc[i][j] += am[i] * bb[j];
            }
            __syncthreads();
        }
    }

    float* dst = g_ctxp[kc];
#pragma unroll
    for (int i = 0; i < 4; i++) {
        float4 r = make_float4(acc[i][0], acc[i][1], acc[i][2], acc[i][3]);
        *(float4*)&dst[(b * TT + t0 + m0 + i) * MD + n0b + n0] = r;
    }
}

// ---------------------------------------------------------------------------
// out_kernel: split-K=3 partials of concat(c,inputs) @ Wout^T.
// kc=0 reads ctx as p0+p1 (folds ctx reduce); kc=1/2 read inputs halves.
// 128x64 tile, 256 threads, 8x4. Grid (8,16,3)=384 blocks.
// ---------------------------------------------------------------------------
__global__ __launch_bounds__(256) void out_kernel(
    const float* __restrict__ inputs, const float* __restrict__ Wout)
{
    __shared__ float As[8][132];
    __shared__ float Bs[8][68];

    const int tid = threadIdx.x;
    const int bm = blockIdx.y * 128;
    const int bn = blockIdx.x * 64;
    const int kc = blockIdx.z;
    const int lrA = tid >> 1;
    const int lcA = (tid & 1) * 4;
    const int tx = tid & 15, ty = tid >> 4;
    const int n0 = tx * 4, m0 = ty * 8;

    const float* p0row = g_ctxp[0] + (bm + lrA) * MD;
    const float* p1row = g_ctxp[1] + (bm + lrA) * MD;
    const float* irow  = inputs + (bm + lrA) * IND + (kc - 1) * 256;
    const float* Wbase = Wout + (bn + lrA) * 768 + kc * 256;

    auto fetchA = [&](int k0) -> float4 {
        if (kc == 0) {
            float4 x = *(const float4*)(p0row + k0 + lcA);
            float4 y = *(const float4*)(p1row + k0 + lcA);
            return make_float4(x.x + y.x, x.y + y.y, x.z + y.z, x.w + y.w);
        }
        return *(const float4*)(irow + k0 + lcA);
    };

    float acc[8][4];
#pragma unroll
    for (int i = 0; i < 8; i++)
#pragma unroll
        for (int j = 0; j < 4; j++) acc[i][j] = 0.f;

    float4 a4 = fetchA(0);
    float4 b4 = make_float4(0.f, 0.f, 0.f, 0.f);
    if (tid < 128) b4 = *(const float4*)(Wbase + lcA);

    for (int k0 = 0; k0 < 256; k0 += 8) {
        As[lcA + 0][lrA] = a4.x; As[lcA + 1][lrA] = a4.y;
        As[lcA + 2][lrA] = a4.z; As[lcA + 3][lrA] = a4.w;
        if (tid < 128) {
            Bs[lcA + 0][lrA] = b4.x; Bs[lcA + 1][lrA] = b4.y;
            Bs[lcA + 2][lrA] = b4.z; Bs[lcA + 3][lrA] = b4.w;
        }
        __syncthreads();
        const int kn = k0 + 8;
        if (kn < 256) {
            a4 = fetchA(kn);
            if (tid < 128) b4 = *(const float4*)(Wbase + kn + lcA);
        }
#pragma unroll
        for (int kk = 0; kk < 8; kk++) {
            float4 x0 = *(const float4*)&As[kk][m0];
            float4 x1 = *(const float4*)&As[kk][m0 + 4];
            float4 y  = *(const float4*)&Bs[kk][n0];
            float am[8] = {x0.x, x0.y, x0.z, x0.w, x1.x, x1.y, x1.z, x1.w};
            float bb[4] = {y.x, y.y, y.z, y.w};
#pragma unroll
            for (int i = 0; i < 8; i++)
#pragma unroll
                for (int j = 0; j < 4; j++) acc[i][j] += am[i] * bb[j];
        }
        __syncthreads();
    }

    float* dst = g_outp[kc];
#pragma unroll
    for (int i = 0; i < 8; i++) {
        float4 r = make_float4(acc[i][0], acc[i][1], acc[i][2], acc[i][3]);
        *(float4*)&dst[(bm + m0 + i) * IND + bn + n0] = r;
    }
}

// ---------------------------------------------------------------------------
// reduce_kernel: out = outp0 + outp1 + outp2 + bias
// ---------------------------------------------------------------------------
__global__ __launch_bounds__(256) void reduce_kernel(
    const float* __restrict__ bout, float* __restrict__ out)
{
    const int idx = blockIdx.x * 256 + threadIdx.x;   // float4 index
    const int e = idx * 4;
    float4 p0 = *(const float4*)&g_outp[0][e];
    float4 p1 = *(const float4*)&g_outp[1][e];
    float4 p2 = *(const float4*)&g_outp[2][e];
    float4 bb = *(const float4*)&bout[e & 511];
    float4 r = make_float4(p0.x + p1.x + p2.x + bb.x,
                           p0.y + p1.y + p2.y + bb.y,
                           p0.z + p1.z + p2.z + bb.z,
                           p0.w + p1.w + p2.w + bb.w);
    *(float4*)&out[e] = r;
}

// ---------------------------------------------------------------------------
extern "C" void kernel_launch(void* const* d_in, const int* in_sizes, int n_in,
                              void* d_out, int out_size)
{
    const float* inputs    = (const float*)d_in[0];
    const float* mems      = (const float*)d_in[1];
    const int*   mem_masks = (const int*)d_in[2];
    const float* Wq        = (const float*)d_in[3];
    const float* Wc        = (const float*)d_in[4];
    const float* bc        = (const float*)d_in[5];
    const float* v         = (const float*)d_in[6];
    const float* Wout      = (const float*)d_in[7];
    const float* bout      = (const float*)d_in[8];

    float* out = (float*)d_out;
    float* pa;
    if (out_size >= BN * TT * IND + BN * TT * SS) {
        pa = out + BN * TT * IND;  // align written in-place in the output
    } else {
        cudaGetSymbolAddress((void**)&pa, g_align_scratch);
    }

    const size_t SMEM_ALIGN = (size_t)(256 * 64 + 16 * 256 + 256) * sizeof(float);
    cudaFuncSetAttribute(align_kernel,
                         cudaFuncAttributeMaxDynamicSharedMemorySize, (int)SMEM_ALIGN);

    proj_kernel<<<dim3(4, 16, 2), 256>>>(inputs, mems, Wq, Wc, bc);
    align_kernel<<<dim3(8, 32, 4), 256, SMEM_ALIGN>>>(mem_masks, v, pa);
    softmax_kernel<<<256, 256>>>(mem_masks, pa);
    ctx_kernel<<<dim3(4, 8, 8), 256>>>(mems, mem_masks, pa);
    out_kernel<<<dim3(8, 16, 3), 256>>>(inputs, Wout);
    reduce_kernel<<<(BN * TT * IND) / (256 * 4), 256>>>(bout, out);
}